// round 7
// baseline (speedup 1.0000x reference)
#include <cuda_runtime.h>

typedef unsigned long long u64;

#define HDIM  64
#define GDIM  256         // 4*HDIM gate rows
#define IDIM  8
#define NTHR  512
#define NP    14          // batch pairs per CTA
#define NB    (2 * NP)    // 28 batches per CTA
#define TP    7           // pairs per team (two teams of 256 threads)
#define NTASK (NP * 128)  // 1792 pointwise tasks
#define NR    4           // pointwise tasks per thread (ceil 1792/512)

// SMEM layout (dynamic):
//  wsm2[kk=32][j=256]  : ulonglong2 { (w[j][2kk],w[j][2kk]) , (w[j][2kk+1],w[j][2kk+1]) }  128 KB
//  gates[NP*GDIM] u64  : 28 KB   | hbuf[NP*HDIM] u64 : 7 KB | xs[2][NP*IDIM] u64 : 1.75 KB
#define WSM2_BYTES  (32 * 256 * 16)              // 131072
#define GATES_BYTES (NP * GDIM * 8)              // 28672
#define HBUF_BYTES  (NP * HDIM * 8)              // 7168
#define XS_BYTES    (2 * NP * IDIM * 8)          // 1792
#define SMEM_BYTES  (WSM2_BYTES + GATES_BYTES + HBUF_BYTES + XS_BYTES)

// ---- packed f32x2 helpers (Blackwell sm_100a) ----
__device__ __forceinline__ u64 ffma2(u64 a, u64 b, u64 c) {
    u64 r;
    asm("fma.rn.f32x2 %0, %1, %2, %3;" : "=l"(r) : "l"(a), "l"(b), "l"(c));
    return r;
}
__device__ __forceinline__ u64 pack2(float x, float y) {
    u64 r;
    asm("mov.b64 %0, {%1, %2};" : "=l"(r) : "f"(x), "f"(y));
    return r;
}

// ---- activations: __expf is MUFU-based, ~1e-7 rel err ----
__device__ __forceinline__ float sigm_f(float x) {
    return 1.0f / (1.0f + __expf(-x));
}
__device__ __forceinline__ float tanh_f(float x) {
    return fmaf(2.0f, 1.0f / (1.0f + __expf(-2.0f * x)), -1.0f);
}

__global__ void __launch_bounds__(NTHR, 1) lstm_persistent_kernel(
    const float* __restrict__ x,      // [B, T, I]
    const float* __restrict__ Wih,    // [4H, I]
    const float* __restrict__ Whh,    // [4H, H]
    const float* __restrict__ bih,    // [4H]
    const float* __restrict__ bhh,    // [4H]
    const float* __restrict__ Wfc,    // [1, H]
    const float* __restrict__ bfc,    // [1]
    float* __restrict__ out,          // [B, 1]
    int B, int T)
{
    extern __shared__ __align__(16) char smem_raw[];
    ulonglong2* wsm2 = (ulonglong2*)smem_raw;                         // [kk*256 + j]
    u64* gates  = (u64*)(smem_raw + WSM2_BYTES);
    u64* hbuf   = (u64*)(smem_raw + WSM2_BYTES + GATES_BYTES);
    u64* xs0    = (u64*)(smem_raw + WSM2_BYTES + GATES_BYTES + HBUF_BYTES);
    u64* xs1    = xs0 + NP * IDIM;

    const int tid  = threadIdx.x;
    const int j    = tid & 255;       // gate row
    const int team = tid >> 8;        // 0 or 1
    const int p0   = team * TP;       // this thread's first batch pair
    const int b0   = blockIdx.x * NB;
    const int nb   = min(NB, B - b0);
    const int nx   = nb * IDIM;

    // ---- stage Whh pre-packed (w,w) into SMEM: wsm2[kk][j] covers k=2kk,2kk+1 ----
    for (int idx = tid; idx < 32 * 256; idx += NTHR) {
        const int kk = idx >> 8, jj = idx & 255;
        float wa = Whh[jj * HDIM + 2 * kk];
        float wb = Whh[jj * HDIM + 2 * kk + 1];
        ulonglong2 e;
        e.x = pack2(wa, wa);
        e.y = pack2(wb, wb);
        wsm2[idx] = e;
    }

    // ---- per-thread input weights + bias ----
    u64 wih2[IDIM];
#pragma unroll
    for (int i = 0; i < IDIM; ++i) {
        float w = Wih[j * IDIM + i];
        wih2[i] = pack2(w, w);
    }
    const float bsum = bih[j] + bhh[j];
    const u64 bias2 = pack2(bsum, bsum);

    // ---- zero h, x buffers (phantom batches stay zero -> bounded values, no OOB) ----
    for (int idx = tid; idx < NP * HDIM; idx += NTHR) hbuf[idx] = 0ull;
    for (int idx = tid; idx < NP * IDIM; idx += NTHR) { xs0[idx] = 0ull; xs1[idx] = 0ull; }

    // ---- pointwise task precompute (time-invariant): idx = tid + NTHR*r ----
    float creg[NR];
    int   goff[NR], hoff[NR];
    bool  pok[NR];
#pragma unroll
    for (int r = 0; r < NR; ++r) {
        const int idx = tid + NTHR * r;
        pok[r] = (idx < NTASK);
        const int p = idx >> 7;
        const int e = (idx >> 6) & 1;
        const int u = idx & 63;
        goff[r] = (p * GDIM + u) * 2 + e;   // float index; +128/+256/+384 for f,g,o
        hoff[r] = (p * HDIM + u) * 2 + e;
        creg[r] = 0.0f;
    }

    // ---- load x(t=0) ----
    int xp = 0, xe = 0, xi = 0;
    if (tid < nx) {
        xp = tid >> 4;
        xe = (tid >> 3) & 1;
        xi = tid & 7;
        float v = x[((size_t)(b0 + 2 * xp + xe) * T) * IDIM + xi];
        ((float*)&xs0[xp * IDIM + xi])[xe] = v;
    }
    __syncthreads();

    const float* gatesf = (const float*)gates;
    float* hbuff = (float*)hbuf;
    const ulonglong2* wrow = wsm2 + j;   // column j; stride 256 entries per kk

    for (int t = 0; t < T; ++t) {
        // prefetch x(t+1)
        float xn = 0.0f;
        const bool do_x = (t + 1 < T) && (tid < nx);
        if (do_x)
            xn = x[((size_t)(b0 + 2 * xp + xe) * T + (t + 1)) * IDIM + xi];

        const u64* xcur = (t & 1) ? xs1 : xs0;

        // ---- acc init: bias + input contribution ----
        u64 acc[TP];
#pragma unroll
        for (int p = 0; p < TP; ++p) {
            const u64* xv = xcur + (p0 + p) * IDIM;
            u64 a = bias2;
#pragma unroll
            for (int i = 0; i < IDIM; i += 2) {
                ulonglong2 xp2 = *(const ulonglong2*)(xv + i);
                a = ffma2(xp2.x, wih2[i], a);
                a = ffma2(xp2.y, wih2[i + 1], a);
            }
            acc[p] = a;
        }

        // ---- matvec: 16 iters x (4 k's); loads front-batched for MLP ----
#pragma unroll
        for (int q = 0; q < 16; ++q) {
            ulonglong2 wA = wrow[(2 * q) * 256];       // k = 4q, 4q+1 (each (w,w))
            ulonglong2 wB = wrow[(2 * q + 1) * 256];   // k = 4q+2, 4q+3
            ulonglong2 hA[TP], hB[TP];
#pragma unroll
            for (int p = 0; p < TP; ++p) {
                const u64* hp = hbuf + (p0 + p) * HDIM + 4 * q;
                hA[p] = *(const ulonglong2*)(hp);
                hB[p] = *(const ulonglong2*)(hp + 2);
            }
#pragma unroll
            for (int p = 0; p < TP; ++p) {
                u64 a = acc[p];
                a = ffma2(hA[p].x, wA.x, a);
                a = ffma2(hA[p].y, wA.y, a);
                a = ffma2(hB[p].x, wB.x, a);
                a = ffma2(hB[p].y, wB.y, a);
                acc[p] = a;
            }
        }

#pragma unroll
        for (int p = 0; p < TP; ++p)
            gates[(p0 + p) * GDIM + j] = acc[p];

        // stash prefetched x (other buffer; visible after barrier)
        if (do_x) {
            u64* xnxt = ((t + 1) & 1) ? xs1 : xs0;
            ((float*)&xnxt[xp * IDIM + xi])[xe] = xn;
        }

        __syncthreads();

        // ---- pointwise: i,f,g,o -> c,h ----
#pragma unroll
        for (int r = 0; r < NR; ++r) {
            if (pok[r]) {
                const int g0 = goff[r];
                float gi = gatesf[g0];
                float gf = gatesf[g0 + 128];
                float gg = gatesf[g0 + 256];
                float go = gatesf[g0 + 384];
                float iv = sigm_f(gi);
                float fv = sigm_f(gf);
                float gv = tanh_f(gg);
                float ov = sigm_f(go);
                float c  = fmaf(fv, creg[r], iv * gv);
                creg[r] = c;
                hbuff[hoff[r]] = ov * tanh_f(c);
            }
        }
        __syncthreads();
    }

    // ---- final FC: out[b] = h_T . Wfc + bfc ----
    if (tid < nb) {
        const int p = tid >> 1, e = tid & 1;
        float sum = bfc[0];
#pragma unroll
        for (int u = 0; u < HDIM; ++u)
            sum = fmaf(hbuff[(p * HDIM + u) * 2 + e], Wfc[u], sum);
        out[b0 + tid] = sum;
    }
}

extern "C" void kernel_launch(void* const* d_in, const int* in_sizes, int n_in,
                              void* d_out, int out_size) {
    const float* x    = (const float*)d_in[0];
    const float* Wih  = (const float*)d_in[1];
    const float* Whh  = (const float*)d_in[2];
    const float* bih  = (const float*)d_in[3];
    const float* bhh  = (const float*)d_in[4];
    const float* Wfc  = (const float*)d_in[5];
    const float* bfc  = (const float*)d_in[6];
    float* out = (float*)d_out;

    const int B = out_size;                   // O = 1
    const int T = in_sizes[0] / (B * IDIM);

    cudaFuncSetAttribute(lstm_persistent_kernel,
                         cudaFuncAttributeMaxDynamicSharedMemorySize, SMEM_BYTES);

    const int grid = (B + NB - 1) / NB;
    lstm_persistent_kernel<<<grid, NTHR, SMEM_BYTES>>>(x, Wih, Whh, bih, bhh, Wfc, bfc, out, B, T);
}

// round 8
// speedup vs baseline: 1.0977x; 1.0977x over previous
#include <cuda_runtime.h>

typedef unsigned long long u64;

#define HDIM  64
#define IDIM  8
#define NTHR  256
#define NPAIR 16          // batch pairs per CTA
#define NB    32          // batches per CTA
#define PPT   4           // pairs per thread (4 q-groups x 64 units)

// SMEM: wsm2[kk=32][j=256] ulonglong2 (pre-packed (w,w) for k=2kk,2kk+1) | h double buf | x double buf
#define WSM2_BYTES (32 * 256 * 16)            // 131072
#define HBUF_BYTES (2 * NPAIR * HDIM * 8)     // 16384
#define XS_BYTES   (2 * NPAIR * IDIM * 8)     // 2048
#define SMEM_BYTES (WSM2_BYTES + HBUF_BYTES + XS_BYTES)

// ---- packed f32x2 helpers (Blackwell sm_100a) ----
__device__ __forceinline__ u64 ffma2(u64 a, u64 b, u64 c) {
    u64 r;
    asm("fma.rn.f32x2 %0, %1, %2, %3;" : "=l"(r) : "l"(a), "l"(b), "l"(c));
    return r;
}
__device__ __forceinline__ u64 pack2(float x, float y) {
    u64 r;
    asm("mov.b64 %0, {%1, %2};" : "=l"(r) : "f"(x), "f"(y));
    return r;
}
__device__ __forceinline__ void unpack2(u64 v, float& lo, float& hi) {
    asm("mov.b64 {%0, %1}, %2;" : "=f"(lo), "=f"(hi) : "l"(v));
}

// ---- activations: __expf is MUFU-based, ~1e-7 rel err ----
__device__ __forceinline__ float sigm_f(float x) {
    return 1.0f / (1.0f + __expf(-x));
}
__device__ __forceinline__ float tanh_f(float x) {
    return fmaf(2.0f, 1.0f / (1.0f + __expf(-2.0f * x)), -1.0f);
}

__global__ void __launch_bounds__(NTHR, 1) lstm_persistent_kernel(
    const float* __restrict__ x,      // [B, T, I]
    const float* __restrict__ Wih,    // [4H, I]
    const float* __restrict__ Whh,    // [4H, H]
    const float* __restrict__ bih,    // [4H]
    const float* __restrict__ bhh,    // [4H]
    const float* __restrict__ Wfc,    // [1, H]
    const float* __restrict__ bfc,    // [1]
    float* __restrict__ out,          // [B, 1]
    int B, int T)
{
    extern __shared__ __align__(16) char smem_raw[];
    ulonglong2* wsm2 = (ulonglong2*)smem_raw;                 // [kk*256 + j]
    u64* hbase = (u64*)(smem_raw + WSM2_BYTES);               // 2 x [pair][unit]
    u64* xbase = (u64*)(smem_raw + WSM2_BYTES + HBUF_BYTES);  // 2 x [pair][feat]

    const int tid = threadIdx.x;
    const int u   = tid & 63;         // hidden unit
    const int q   = tid >> 6;         // pair group 0..3
    const int pb  = q * PPT;          // first pair of this thread
    const int b0  = blockIdx.x * NB;
    const int nb  = min(NB, B - b0);
    const int nx  = nb * IDIM;

    // ---- stage Whh pre-packed (w,w): wsm2[kk][j] covers k=2kk,2kk+1 ----
    for (int idx = tid; idx < 32 * 256; idx += NTHR) {
        const int kk = idx >> 8, j = idx & 255;
        float wa = Whh[j * HDIM + 2 * kk];
        float wb = Whh[j * HDIM + 2 * kk + 1];
        ulonglong2 e;
        e.x = pack2(wa, wa);
        e.y = pack2(wb, wb);
        wsm2[idx] = e;
    }

    // ---- per-thread Wih rows (gate rows u, u+64, u+128, u+192) + biases ----
    u64 wih2[4][IDIM];
    u64 bias2[4];
#pragma unroll
    for (int g = 0; g < 4; ++g) {
        const int row = u + 64 * g;
#pragma unroll
        for (int i = 0; i < IDIM; ++i) {
            float w = Wih[row * IDIM + i];
            wih2[g][i] = pack2(w, w);
        }
        float b = bih[row] + bhh[row];
        bias2[g] = pack2(b, b);
    }

    // ---- zero h (both buffers) and x buffers; phantom batches stay bounded ----
    for (int idx = tid; idx < 2 * NPAIR * HDIM; idx += NTHR) hbase[idx] = 0ull;
    for (int idx = tid; idx < 2 * NPAIR * IDIM; idx += NTHR) xbase[idx] = 0ull;

    // ---- cell state in registers: c[pair][even/odd] ----
    float ce[PPT], co[PPT];
#pragma unroll
    for (int p = 0; p < PPT; ++p) { ce[p] = 0.0f; co[p] = 0.0f; }

    // ---- load x(t=0): 256 threads == 32 batches x 8 features exactly ----
    int xp = 0, xe = 0, xi = 0;
    if (tid < nx) {
        xp = tid >> 4;            // pair
        xe = (tid >> 3) & 1;      // half within pair
        xi = tid & 7;             // feature
        float v = x[((size_t)(b0 + 2 * xp + xe) * T) * IDIM + xi];
        ((float*)&xbase[xp * IDIM + xi])[xe] = v;
    }
    __syncthreads();

    for (int t = 0; t < T; ++t) {
        // prefetch x(t+1)
        float xn = 0.0f;
        const bool do_x = (t + 1 < T) && (tid < nx);
        if (do_x)
            xn = x[((size_t)(b0 + 2 * xp + xe) * T + (t + 1)) * IDIM + xi];

        const u64* hcur = hbase + (t & 1) * (NPAIR * HDIM);
        u64*       hnxt = hbase + ((t + 1) & 1) * (NPAIR * HDIM);
        const u64* xcur = xbase + (t & 1) * (NPAIR * IDIM);
        u64*       xnxt = xbase + ((t + 1) & 1) * (NPAIR * IDIM);

        // ---- acc init: bias + Wih.x  (16 independent chains) ----
        u64 acc[4][PPT];
#pragma unroll
        for (int p = 0; p < PPT; ++p) {
            const u64* xv = xcur + (pb + p) * IDIM;
            ulonglong2 x0 = *(const ulonglong2*)(xv);
            ulonglong2 x1 = *(const ulonglong2*)(xv + 2);
            ulonglong2 x2 = *(const ulonglong2*)(xv + 4);
            ulonglong2 x3 = *(const ulonglong2*)(xv + 6);
#pragma unroll
            for (int g = 0; g < 4; ++g) {
                u64 a = bias2[g];
                a = ffma2(x0.x, wih2[g][0], a);
                a = ffma2(x0.y, wih2[g][1], a);
                a = ffma2(x1.x, wih2[g][2], a);
                a = ffma2(x1.y, wih2[g][3], a);
                a = ffma2(x2.x, wih2[g][4], a);
                a = ffma2(x2.y, wih2[g][5], a);
                a = ffma2(x3.x, wih2[g][6], a);
                a = ffma2(x3.y, wih2[g][7], a);
                acc[g][p] = a;
            }
        }

        // ---- matvec main: 32 iters, 8 LDS.128 + 32 FFMA2 each ----
#pragma unroll
        for (int kk = 0; kk < 32; ++kk) {
            ulonglong2 wv[4];
#pragma unroll
            for (int g = 0; g < 4; ++g)
                wv[g] = wsm2[kk * 256 + u + 64 * g];
            ulonglong2 hv[PPT];
#pragma unroll
            for (int p = 0; p < PPT; ++p)
                hv[p] = *(const ulonglong2*)(hcur + (pb + p) * HDIM + 2 * kk);
#pragma unroll
            for (int p = 0; p < PPT; ++p) {
#pragma unroll
                for (int g = 0; g < 4; ++g) {
                    u64 a = acc[g][p];
                    a = ffma2(hv[p].x, wv[g].x, a);
                    a = ffma2(hv[p].y, wv[g].y, a);
                    acc[g][p] = a;
                }
            }
        }

        // stash prefetched x (other buffer)
        if (do_x)
            ((float*)&xnxt[xp * IDIM + xi])[xe] = xn;

        // ---- pointwise IN REGISTERS: i,f,g,o -> c,h; write h to next buffer ----
#pragma unroll
        for (int p = 0; p < PPT; ++p) {
            float gie, gio, gfe, gfo, gge, ggo, goe, goo;
            unpack2(acc[0][p], gie, gio);
            unpack2(acc[1][p], gfe, gfo);
            unpack2(acc[2][p], gge, ggo);
            unpack2(acc[3][p], goe, goo);

            float iv = sigm_f(gie);
            float fv = sigm_f(gfe);
            float gv = tanh_f(gge);
            float ov = sigm_f(goe);
            float c  = fmaf(fv, ce[p], iv * gv);
            ce[p] = c;
            float he = ov * tanh_f(c);

            iv = sigm_f(gio);
            fv = sigm_f(gfo);
            gv = tanh_f(ggo);
            ov = sigm_f(goo);
            c  = fmaf(fv, co[p], iv * gv);
            co[p] = c;
            float ho = ov * tanh_f(c);

            hnxt[(pb + p) * HDIM + u] = pack2(he, ho);
        }
        __syncthreads();   // single barrier per step
    }

    // ---- final FC: out[b] = h_T . Wfc + bfc ----
    const u64* hfin = hbase + (T & 1) * (NPAIR * HDIM);
    if (tid < nb) {
        const int p = tid >> 1, e = tid & 1;
        float s = bfc[0];
#pragma unroll
        for (int k = 0; k < HDIM; ++k)
            s = fmaf(((const float*)&hfin[p * HDIM + k])[e], Wfc[k], s);
        out[b0 + tid] = s;
    }
}

extern "C" void kernel_launch(void* const* d_in, const int* in_sizes, int n_in,
                              void* d_out, int out_size) {
    const float* x    = (const float*)d_in[0];
    const float* Wih  = (const float*)d_in[1];
    const float* Whh  = (const float*)d_in[2];
    const float* bih  = (const float*)d_in[3];
    const float* bhh  = (const float*)d_in[4];
    const float* Wfc  = (const float*)d_in[5];
    const float* bfc  = (const float*)d_in[6];
    float* out = (float*)d_out;

    const int B = out_size;                   // O = 1
    const int T = in_sizes[0] / (B * IDIM);

    cudaFuncSetAttribute(lstm_persistent_kernel,
                         cudaFuncAttributeMaxDynamicSharedMemorySize, SMEM_BYTES);

    const int grid = (B + NB - 1) / NB;
    lstm_persistent_kernel<<<grid, NTHR, SMEM_BYTES>>>(x, Wih, Whh, bih, bhh, Wfc, bfc, out, B, T);
}